// round 2
// baseline (speedup 1.0000x reference)
#include <cuda_runtime.h>
#include <math.h>

#define B 8
#define N 256
#define BN 2048
#define NID 64
#define V 128
#define GH 128
#define PHI 256
#define RHO 128
#define EPS 1e-5f
#define RT 16                 // rows per block
#define NBLK (BN / RT)        // 128 blocks

// ---------------- scratch ----------------
__device__ float g_H[BN * GH];
__device__ float g_H2[BN * GH];
__device__ float g_agg[BN * GH];
__device__ float g_Spos[BN * GH];
__device__ float g_Sneg[BN * GH];
__device__ float g_phi[BN * PHI];
__device__ float g_sums[4 * 2 * B * PHI];   // [seg][home/away][b][p]

// ---------------- K1: embedding ----------------
__global__ void k_emb(const float* __restrict__ X,
                      const float* __restrict__ W1, const float* __restrict__ b1,
                      const float* __restrict__ W2, const float* __restrict__ b2) {
    int r0 = blockIdx.x * RT;
    int t = threadIdx.x;          // 128
    __shared__ float xs[RT][NID];
    __shared__ float h1[RT][V];
    for (int idx = t; idx < RT * NID; idx += 128) {
        int rr = idx >> 6, kk = idx & 63;
        xs[rr][kk] = X[(r0 + rr) * NID + kk];
    }
    __syncthreads();
    float acc[RT];
    float bb = b1[t];
#pragma unroll
    for (int r = 0; r < RT; r++) acc[r] = bb;
#pragma unroll 4
    for (int k = 0; k < NID; k++) {
        float w = W1[k * V + t];
#pragma unroll
        for (int r = 0; r < RT; r++) acc[r] = fmaf(xs[r][k], w, acc[r]);
    }
#pragma unroll
    for (int r = 0; r < RT; r++) h1[r][t] = fmaxf(acc[r], 0.f);
    __syncthreads();
    bb = b2[t];
#pragma unroll
    for (int r = 0; r < RT; r++) acc[r] = bb;
#pragma unroll 4
    for (int k = 0; k < V; k++) {
        float w = W2[k * V + t];
#pragma unroll
        for (int r = 0; r < RT; r++) acc[r] = fmaf(h1[r][k], w, acc[r]);
    }
#pragma unroll
    for (int r = 0; r < RT; r++) g_H[(r0 + r) * V + t] = acc[r];
}

// ---------------- K2: RGCN masked reduce over sources ----------------
// block = (b, jtile of 16). Computes normalized s_neg/s_pos for 16 target nodes.
__global__ void k_reduce(const float* __restrict__ A) {
    int b = blockIdx.x >> 4;
    int j0 = (blockIdx.x & 15) * 16;
    int t = threadIdx.x;          // 128
    __shared__ float mp[16][16], mn[16][16];
    __shared__ float pc[8][16][2];
    __shared__ float rcp[16][2];

    float accP[16], accN[16];
#pragma unroll
    for (int j = 0; j < 16; j++) { accP[j] = 0.f; accN[j] = 0.f; }

    const float* Ab = A + b * N * N;
    for (int i0 = 0; i0 < N; i0 += 16) {
        for (int idx = t; idx < 256; idx += 128) {
            int ii = idx >> 4, jj = idx & 15;
            float a = Ab[(i0 + ii) * N + j0 + jj];
            mp[ii][jj] = (a > 0.f) ? 1.f : 0.f;
            mn[ii][jj] = (a < 0.f) ? 1.f : 0.f;
        }
        __syncthreads();
#pragma unroll
        for (int ii = 0; ii < 16; ii++) {
            float h = g_H[((b << 8) + i0 + ii) * V + t];
#pragma unroll
            for (int j = 0; j < 16; j++) {
                accP[j] = fmaf(mp[ii][j], h, accP[j]);
                accN[j] = fmaf(mn[ii][j], h, accN[j]);
            }
        }
        __syncthreads();
    }
    // counts: 8 segments x 16 j
    {
        int seg = t >> 4, j = t & 15;
        float cp = 0.f, cn = 0.f;
        for (int i = seg; i < N; i += 8) {
            float a = Ab[i * N + j0 + j];
            cp += (a > 0.f) ? 1.f : 0.f;
            cn += (a < 0.f) ? 1.f : 0.f;
        }
        pc[seg][j][0] = cp; pc[seg][j][1] = cn;
    }
    __syncthreads();
    if (t < 16) {
        float cp = 0.f, cn = 0.f;
#pragma unroll
        for (int s = 0; s < 8; s++) { cp += pc[s][t][0]; cn += pc[s][t][1]; }
        rcp[t][0] = 1.f / fmaxf(cp, 1.f);
        rcp[t][1] = 1.f / fmaxf(cn, 1.f);
    }
    __syncthreads();
#pragma unroll
    for (int j = 0; j < 16; j++) {
        int row = (b << 8) + j0 + j;
        g_Spos[row * V + t] = accP[j] * rcp[j][0];
        g_Sneg[row * V + t] = accN[j] * rcp[j][1];
    }
}

// ---------------- K3: RGCN matmuls (root + 2 relations) ----------------
__global__ void k_rgcnmm(const float* __restrict__ Wrel,
                         const float* __restrict__ Wroot,
                         const float* __restrict__ bias) {
    int r0 = blockIdx.x * RT;
    int t = threadIdx.x;          // 128
    __shared__ float hr[RT][GH], sn[RT][GH], sp[RT][GH];
    for (int idx = t; idx < RT * GH; idx += 128) {
        int rr = idx >> 7, kk = idx & 127;
        int row = (r0 + rr) * GH + kk;
        hr[rr][kk] = g_H[row];
        sn[rr][kk] = g_Sneg[row];
        sp[rr][kk] = g_Spos[row];
    }
    __syncthreads();
    const float* W0 = Wrel;
    const float* W1 = Wrel + V * GH;
    float acc[RT];
    float bb = bias[t];
#pragma unroll
    for (int r = 0; r < RT; r++) acc[r] = bb;
#pragma unroll 2
    for (int k = 0; k < GH; k++) {
        float wr = Wroot[k * GH + t];
        float w0 = W0[k * GH + t];
        float w1 = W1[k * GH + t];
#pragma unroll
        for (int r = 0; r < RT; r++) {
            float a = acc[r];
            a = fmaf(hr[r][k], wr, a);
            a = fmaf(sn[r][k], w0, a);
            a = fmaf(sp[r][k], w1, a);
            acc[r] = a;
        }
    }
#pragma unroll
    for (int r = 0; r < RT; r++) g_H2[(r0 + r) * GH + t] = acc[r];
}

// ---------------- K4: scatter  agg[b,i,:] = sum_j |A[b,i,j]| * H2[b,j,:] ----------------
__global__ void k_scatter(const float* __restrict__ A) {
    int b = blockIdx.x >> 4;
    int i0 = (blockIdx.x & 15) * 16;
    int t = threadIdx.x;          // 128
    __shared__ float aab[16][32];
    float acc[16];
#pragma unroll
    for (int r = 0; r < 16; r++) acc[r] = 0.f;
    const float* Ab = A + b * N * N;
    for (int jc = 0; jc < N; jc += 32) {
        for (int idx = t; idx < 512; idx += 128) {
            int ii = idx >> 5, jj = idx & 31;
            aab[ii][jj] = fabsf(Ab[(i0 + ii) * N + jc + jj]);
        }
        __syncthreads();
#pragma unroll 4
        for (int jj = 0; jj < 32; jj++) {
            float h2 = g_H2[((b << 8) + jc + jj) * GH + t];
#pragma unroll
            for (int r = 0; r < 16; r++) acc[r] = fmaf(aab[r][jj], h2, acc[r]);
        }
        __syncthreads();
    }
#pragma unroll
    for (int r = 0; r < 16; r++) g_agg[((b << 8) + i0 + r) * GH + t] = acc[r];
}

// ---------------- K5: layernorm + relu + 2-layer MLP, fused H += result ----------------
__global__ void k_normmlp(const float* __restrict__ norm_g, const float* __restrict__ norm_b,
                          const float* __restrict__ law, const float* __restrict__ lab,
                          const float* __restrict__ lbw, const float* __restrict__ lbb) {
    int r0 = blockIdx.x * RT;
    int t = threadIdx.x;          // 128
    int warp = t >> 5, lane = t & 31;
    __shared__ float buf[RT][GH];
    __shared__ float stat[RT][2];

#pragma unroll
    for (int r = 0; r < RT; r++) buf[r][t] = g_agg[(r0 + r) * GH + t];
    __syncthreads();

    // stats: each warp does 4 rows
#pragma unroll
    for (int rr = 0; rr < 4; rr++) {
        int r = warp * 4 + rr;
        float s = 0.f, sq = 0.f;
#pragma unroll
        for (int c = 0; c < 4; c++) {
            float v = buf[r][lane + c * 32];
            s += v; sq = fmaf(v, v, sq);
        }
#pragma unroll
        for (int o = 16; o > 0; o >>= 1) {
            s  += __shfl_xor_sync(0xffffffff, s, o);
            sq += __shfl_xor_sync(0xffffffff, sq, o);
        }
        if (lane == 0) {
            float mean = s * (1.f / GH);
            float var = sq * (1.f / GH) - mean * mean;
            stat[r][0] = mean;
            stat[r][1] = rsqrtf(var + EPS);
        }
    }
    __syncthreads();
    float g = norm_g[t], bb = norm_b[t];
#pragma unroll
    for (int r = 0; r < RT; r++) {
        float v = (buf[r][t] - stat[r][0]) * stat[r][1] * g + bb;
        buf[r][t] = fmaxf(v, 0.f);
    }
    __syncthreads();

    float acc[RT];
    float bias = lab[t];
#pragma unroll
    for (int r = 0; r < RT; r++) acc[r] = bias;
#pragma unroll 4
    for (int k = 0; k < GH; k++) {
        float w = law[k * GH + t];
#pragma unroll
        for (int r = 0; r < RT; r++) acc[r] = fmaf(buf[r][k], w, acc[r]);
    }
    __syncthreads();
#pragma unroll
    for (int r = 0; r < RT; r++) buf[r][t] = fmaxf(acc[r], 0.f);
    __syncthreads();

    bias = lbb[t];
#pragma unroll
    for (int r = 0; r < RT; r++) acc[r] = bias;
#pragma unroll 4
    for (int k = 0; k < GH; k++) {
        float w = lbw[k * GH + t];
#pragma unroll
        for (int r = 0; r < RT; r++) acc[r] = fmaf(buf[r][k], w, acc[r]);
    }
#pragma unroll
    for (int r = 0; r < RT; r++) g_H[(r0 + r) * GH + t] += acc[r];   // fused H += agg
}

// ---------------- K6: phi MLP ----------------
__global__ void k_phi(const float* __restrict__ w1, const float* __restrict__ b1,
                      const float* __restrict__ w2, const float* __restrict__ b2) {
    int r0 = blockIdx.x * RT;
    int t = threadIdx.x;          // 256
    __shared__ float hf[RT][GH];
    __shared__ float h1[RT][PHI];
    for (int idx = t; idx < RT * GH; idx += 256) {
        int rr = idx >> 7, kk = idx & 127;
        hf[rr][kk] = g_H[(r0 + rr) * GH + kk];
    }
    __syncthreads();
    float acc[RT];
    float bb = b1[t];
#pragma unroll
    for (int r = 0; r < RT; r++) acc[r] = bb;
#pragma unroll 4
    for (int k = 0; k < GH; k++) {
        float w = w1[k * PHI + t];
#pragma unroll
        for (int r = 0; r < RT; r++) acc[r] = fmaf(hf[r][k], w, acc[r]);
    }
#pragma unroll
    for (int r = 0; r < RT; r++) h1[r][t] = fmaxf(acc[r], 0.f);
    __syncthreads();
    bb = b2[t];
#pragma unroll
    for (int r = 0; r < RT; r++) acc[r] = bb;
#pragma unroll 4
    for (int k = 0; k < PHI; k++) {
        float w = w2[k * PHI + t];
#pragma unroll
        for (int r = 0; r < RT; r++) acc[r] = fmaf(h1[r][k], w, acc[r]);
    }
#pragma unroll
    for (int r = 0; r < RT; r++) g_phi[(r0 + r) * PHI + t] = fmaxf(acc[r], 0.f);
}

// ---------------- K7: masked pooling (4 segments of 64 nodes) ----------------
__global__ void k_pool(const float* __restrict__ home_mask) {
    int b = blockIdx.x;
    int seg = blockIdx.y;
    int p = threadIdx.x;          // 256
    const float* pb = g_phi + b * N * PHI;
    const float* hm = home_mask + b * N;
    float hs = 0.f, as = 0.f;
    int n0 = seg * 64;
    for (int n = n0; n < n0 + 64; n++) {
        float v = pb[n * PHI + p];
        float m = hm[n];
        hs = fmaf(v, m, hs);
        as = fmaf(v, 1.f - m, as);
    }
    g_sums[((seg * 2 + 0) * B + b) * PHI + p] = hs;
    g_sums[((seg * 2 + 1) * B + b) * PHI + p] = as;
}

// ---------------- K8: rho head ----------------
__global__ void k_rho(const float* __restrict__ w1, const float* __restrict__ b1,
                      const float* __restrict__ w2, float* __restrict__ out) {
    int b = blockIdx.x;           // 8
    int t = threadIdx.x;          // 128
    __shared__ float hs[PHI];
    __shared__ float as[PHI];
    __shared__ float red[RHO];
    for (int c = t; c < PHI; c += 128) {
        float h = 0.f, a = 0.f;
#pragma unroll
        for (int seg = 0; seg < 4; seg++) {
            h += g_sums[((seg * 2 + 0) * B + b) * PHI + c];
            a += g_sums[((seg * 2 + 1) * B + b) * PHI + c];
        }
        hs[c] = h; as[c] = a;
    }
    __syncthreads();
    float rh = b1[t], ra = b1[t];
#pragma unroll 4
    for (int k = 0; k < PHI; k++) {
        rh = fmaf(hs[k], w1[k * RHO + t], rh);
        ra = fmaf(as[k], w1[k * RHO + t], ra);
    }
    rh = fmaxf(rh, 0.f);
    ra = fmaxf(ra, 0.f);
    red[t] = (rh - ra) * w2[t];
    __syncthreads();
    for (int s = RHO / 2; s > 0; s >>= 1) {
        if (t < s) red[t] += red[t + s];
        __syncthreads();
    }
    if (t == 0) out[b] = 0.5f + 0.5f * tanhf(red[0]);
}

// ---------------- launch ----------------
extern "C" void kernel_launch(void* const* d_in, const int* in_sizes, int n_in,
                              void* d_out, int out_size) {
    const float* A        = (const float*)d_in[0];
    const float* X        = (const float*)d_in[1];
    const float* home     = (const float*)d_in[2];
    const float* emb1_w   = (const float*)d_in[3];
    const float* emb1_b   = (const float*)d_in[4];
    const float* emb2_w   = (const float*)d_in[5];
    const float* emb2_b   = (const float*)d_in[6];
    const float* rgcn_w0  = (const float*)d_in[7];
    const float* root0    = (const float*)d_in[8];
    const float* bias0    = (const float*)d_in[9];
    const float* law0     = (const float*)d_in[10];
    const float* lab0     = (const float*)d_in[11];
    const float* lbw0     = (const float*)d_in[12];
    const float* lbb0     = (const float*)d_in[13];
    const float* rgcn_w1  = (const float*)d_in[14];
    const float* root1    = (const float*)d_in[15];
    const float* bias1    = (const float*)d_in[16];
    const float* law1     = (const float*)d_in[17];
    const float* lab1     = (const float*)d_in[18];
    const float* lbw1     = (const float*)d_in[19];
    const float* lbb1     = (const float*)d_in[20];
    const float* norm_g   = (const float*)d_in[21];
    const float* norm_b   = (const float*)d_in[22];
    const float* phi_w1   = (const float*)d_in[23];
    const float* phi_b1   = (const float*)d_in[24];
    const float* phi_w2   = (const float*)d_in[25];
    const float* phi_b2   = (const float*)d_in[26];
    const float* rho_w1   = (const float*)d_in[27];
    const float* rho_b1   = (const float*)d_in[28];
    const float* rho_w2   = (const float*)d_in[29];
    float* out = (float*)d_out;

    k_emb<<<NBLK, 128>>>(X, emb1_w, emb1_b, emb2_w, emb2_b);

    // block 0
    k_reduce<<<NBLK, 128>>>(A);
    k_rgcnmm<<<NBLK, 128>>>(rgcn_w0, root0, bias0);
    k_scatter<<<NBLK, 128>>>(A);
    k_normmlp<<<NBLK, 128>>>(norm_g, norm_b, law0, lab0, lbw0, lbb0); // H += agg0

    // block 1
    k_reduce<<<NBLK, 128>>>(A);
    k_rgcnmm<<<NBLK, 128>>>(rgcn_w1, root1, bias1);
    k_scatter<<<NBLK, 128>>>(A);
    k_normmlp<<<NBLK, 128>>>(norm_g, norm_b, law1, lab1, lbw1, lbb1); // H += agg1

    k_phi<<<NBLK, 256>>>(phi_w1, phi_b1, phi_w2, phi_b2);
    dim3 pg(B, 4);
    k_pool<<<pg, 256>>>(home);
    k_rho<<<B, 128>>>(rho_w1, rho_b1, rho_w2, out);
}

// round 4
// speedup vs baseline: 1.4157x; 1.4157x over previous
#include <cuda_runtime.h>
#include <math.h>

#define B 8
#define N 256
#define BN 2048
#define NID 64
#define V 128
#define GH 128
#define PHI 256
#define RHO 128
#define EPS 1e-5f
#define RT 8                  // rows per block
#define NBLK (BN / RT)        // 256 blocks

// ---------------- scratch ----------------
__device__ float g_H[BN * GH];
__device__ float g_H2[BN * GH];
__device__ float g_agg[BN * GH];
__device__ float g_Spos[BN * GH];
__device__ float g_Sneg[BN * GH];
__device__ float g_phi[BN * PHI];
__device__ float g_sums[8 * 2 * B * PHI];   // [seg][home/away][b][p]

// ---------------- K1: embedding  H = relu(X@W1+b1)@W2+b2 ----------------
__global__ void k_emb(const float* __restrict__ X,
                      const float* __restrict__ W1, const float* __restrict__ b1,
                      const float* __restrict__ W2, const float* __restrict__ b2) {
    int r0 = blockIdx.x * RT;
    int t = threadIdx.x;              // 256
    int col = t & 127, rg = t >> 7;   // rowgroup: rows rg*4 .. rg*4+3
    __shared__ __align__(16) float xsT[NID * 12];   // [k][row], stride 12
    __shared__ __align__(16) float h1T[V * 12];

    for (int idx = t; idx < RT * NID; idx += 256) {
        int rr = idx >> 6, kk = idx & 63;
        xsT[kk * 12 + rr] = X[(r0 + rr) * NID + kk];
    }
    __syncthreads();

    float a0, a1, a2, a3;
    a0 = a1 = a2 = a3 = b1[col];
#pragma unroll 4
    for (int k = 0; k < NID; k++) {
        float w = W1[k * V + col];
        float4 x = *(const float4*)&xsT[k * 12 + rg * 4];
        a0 = fmaf(x.x, w, a0); a1 = fmaf(x.y, w, a1);
        a2 = fmaf(x.z, w, a2); a3 = fmaf(x.w, w, a3);
    }
    {
        float4 h = make_float4(fmaxf(a0, 0.f), fmaxf(a1, 0.f), fmaxf(a2, 0.f), fmaxf(a3, 0.f));
        *(float4*)&h1T[col * 12 + rg * 4] = h;
    }
    __syncthreads();

    a0 = a1 = a2 = a3 = b2[col];
#pragma unroll 4
    for (int k = 0; k < V; k++) {
        float w = W2[k * V + col];
        float4 x = *(const float4*)&h1T[k * 12 + rg * 4];
        a0 = fmaf(x.x, w, a0); a1 = fmaf(x.y, w, a1);
        a2 = fmaf(x.z, w, a2); a3 = fmaf(x.w, w, a3);
    }
    int base = (r0 + rg * 4) * V + col;
    g_H[base] = a0; g_H[base + V] = a1; g_H[base + 2 * V] = a2; g_H[base + 3 * V] = a3;
}

// ---------------- K2: RGCN masked mean over sources ----------------
// block = (b, j-tile of 8); 256 threads = 2 i-segments x 128 cols
__global__ void k_reduce(const float* __restrict__ A) {
    int b = blockIdx.x >> 5;
    int j0 = (blockIdx.x & 31) * 8;
    int t = threadIdx.x;
    int col = t & 127, iseg = t >> 7;
    int wp = t >> 5, lane = t & 31;

    __shared__ float2 mpn[N][8];
    __shared__ float sumP[8][128], sumN[8][128];
    __shared__ float rcp2[8][2];

    const float* Ab = A + b * N * N;
    // stage masks: thread handles jj = t&7, rows (t>>3) + 32*it
    {
        int jj = t & 7, ib = t >> 3;
#pragma unroll
        for (int it = 0; it < 8; it++) {
            int i = ib + it * 32;
            float a = Ab[i * N + j0 + jj];
            mpn[i][jj] = make_float2((a > 0.f) ? 1.f : 0.f, (a < 0.f) ? 1.f : 0.f);
        }
    }
    __syncthreads();

    // counts: warp w handles jj = w
    {
        float cp = 0.f, cn = 0.f;
        for (int i = lane; i < N; i += 32) {
            float2 m = mpn[i][wp];
            cp += m.x; cn += m.y;
        }
#pragma unroll
        for (int o = 16; o > 0; o >>= 1) {
            cp += __shfl_xor_sync(0xffffffff, cp, o);
            cn += __shfl_xor_sync(0xffffffff, cn, o);
        }
        if (lane == 0) {
            rcp2[wp][0] = 1.f / fmaxf(cp, 1.f);
            rcp2[wp][1] = 1.f / fmaxf(cn, 1.f);
        }
    }

    float accP[8], accN[8];
#pragma unroll
    for (int j = 0; j < 8; j++) { accP[j] = 0.f; accN[j] = 0.f; }

    const float* Hb = g_H + ((b << 8) + (iseg << 7)) * V + col;
#pragma unroll 2
    for (int ii = 0; ii < 128; ii++) {
        float h = Hb[ii * V];
        int i = (iseg << 7) + ii;
#pragma unroll
        for (int jj = 0; jj < 8; jj++) {
            float2 m = mpn[i][jj];
            accP[jj] = fmaf(m.x, h, accP[jj]);
            accN[jj] = fmaf(m.y, h, accN[jj]);
        }
    }

    if (iseg) {
#pragma unroll
        for (int jj = 0; jj < 8; jj++) { sumP[jj][col] = accP[jj]; sumN[jj][col] = accN[jj]; }
    }
    __syncthreads();
    if (!iseg) {
#pragma unroll
        for (int jj = 0; jj < 8; jj++) {
            int row = (b << 8) + j0 + jj;
            g_Spos[row * V + col] = (accP[jj] + sumP[jj][col]) * rcp2[jj][0];
            g_Sneg[row * V + col] = (accN[jj] + sumN[jj][col]) * rcp2[jj][1];
        }
    }
}

// ---------------- K3: RGCN matmuls ----------------
__global__ void k_rgcnmm(const float* __restrict__ Wrel,
                         const float* __restrict__ Wroot,
                         const float* __restrict__ bias) {
    int r0 = blockIdx.x * RT;
    int t = threadIdx.x;
    int col = t & 127, rg = t >> 7;
    __shared__ __align__(16) float hrT[GH * 12];
    __shared__ __align__(16) float snT[GH * 12];
    __shared__ __align__(16) float spT[GH * 12];

    for (int idx = t; idx < RT * GH; idx += 256) {
        int rr = idx >> 7, kk = idx & 127;
        int row = (r0 + rr) * GH + kk;
        hrT[kk * 12 + rr] = g_H[row];
        snT[kk * 12 + rr] = g_Sneg[row];
        spT[kk * 12 + rr] = g_Spos[row];
    }
    __syncthreads();

    const float* W0 = Wrel;
    const float* W1 = Wrel + V * GH;
    float a0, a1, a2, a3;
    a0 = a1 = a2 = a3 = bias[col];
#pragma unroll 2
    for (int k = 0; k < GH; k++) {
        float wr = Wroot[k * GH + col];
        float w0 = W0[k * GH + col];
        float w1 = W1[k * GH + col];
        float4 h = *(const float4*)&hrT[k * 12 + rg * 4];
        float4 sn = *(const float4*)&snT[k * 12 + rg * 4];
        float4 sp = *(const float4*)&spT[k * 12 + rg * 4];
        a0 = fmaf(h.x, wr, a0); a1 = fmaf(h.y, wr, a1); a2 = fmaf(h.z, wr, a2); a3 = fmaf(h.w, wr, a3);
        a0 = fmaf(sn.x, w0, a0); a1 = fmaf(sn.y, w0, a1); a2 = fmaf(sn.z, w0, a2); a3 = fmaf(sn.w, w0, a3);
        a0 = fmaf(sp.x, w1, a0); a1 = fmaf(sp.y, w1, a1); a2 = fmaf(sp.z, w1, a2); a3 = fmaf(sp.w, w1, a3);
    }
    int base = (r0 + rg * 4) * GH + col;
    g_H2[base] = a0; g_H2[base + GH] = a1; g_H2[base + 2 * GH] = a2; g_H2[base + 3 * GH] = a3;
}

// ---------------- K4: scatter agg[b,i,:] = sum_j |A[b,i,j]|*H2[b,j,:] ----------------
// block = (b, i-tile of 8); 256 threads = 2 j-segments x 128 cols
__global__ void k_scatter(const float* __restrict__ A) {
    int b = blockIdx.x >> 5;
    int i0 = (blockIdx.x & 31) * 8;
    int t = threadIdx.x;
    int col = t & 127, jseg = t >> 7;
    __shared__ __align__(16) float aabT[N * 8];   // [j][i] i in tile
    __shared__ float sumb[8][128];

    {
        int jj = t;   // 0..255
        const float* Ar = A + (b * N + i0) * N + jj;
        float a[8];
#pragma unroll
        for (int q = 0; q < 8; q++) a[q] = fabsf(Ar[q * N]);
        *(float4*)&aabT[jj * 8] = make_float4(a[0], a[1], a[2], a[3]);
        *(float4*)&aabT[jj * 8 + 4] = make_float4(a[4], a[5], a[6], a[7]);
    }
    __syncthreads();

    float acc[8];
#pragma unroll
    for (int q = 0; q < 8; q++) acc[q] = 0.f;
    const float* H2b = g_H2 + ((b << 8) + (jseg << 7)) * GH + col;
#pragma unroll 2
    for (int jj = 0; jj < 128; jj++) {
        float h2 = H2b[jj * GH];
        int j = (jseg << 7) + jj;
        float4 m1 = *(const float4*)&aabT[j * 8];
        float4 m2 = *(const float4*)&aabT[j * 8 + 4];
        acc[0] = fmaf(m1.x, h2, acc[0]); acc[1] = fmaf(m1.y, h2, acc[1]);
        acc[2] = fmaf(m1.z, h2, acc[2]); acc[3] = fmaf(m1.w, h2, acc[3]);
        acc[4] = fmaf(m2.x, h2, acc[4]); acc[5] = fmaf(m2.y, h2, acc[5]);
        acc[6] = fmaf(m2.z, h2, acc[6]); acc[7] = fmaf(m2.w, h2, acc[7]);
    }
    if (jseg) {
#pragma unroll
        for (int q = 0; q < 8; q++) sumb[q][col] = acc[q];
    }
    __syncthreads();
    if (!jseg) {
#pragma unroll
        for (int q = 0; q < 8; q++)
            g_agg[((b << 8) + i0 + q) * GH + col] = acc[q] + sumb[q][col];
    }
}

// ---------------- K5: layernorm+relu+MLP, fused H += out ----------------
__global__ void k_normmlp(const float* __restrict__ norm_g, const float* __restrict__ norm_b,
                          const float* __restrict__ law, const float* __restrict__ lab,
                          const float* __restrict__ lbw, const float* __restrict__ lbb) {
    int r0 = blockIdx.x * RT;
    int t = threadIdx.x;
    int col = t & 127, rg = t >> 7;
    int wp = t >> 5, lane = t & 31;
    __shared__ float buf[RT][GH];
    __shared__ __align__(16) float bufT[GH * 12];
    __shared__ float stat[RT][2];

    for (int idx = t; idx < RT * GH; idx += 256) {
        int rr = idx >> 7, cc = idx & 127;
        buf[rr][cc] = g_agg[(r0 + rr) * GH + cc];
    }
    __syncthreads();

    // stats: warp w -> row w
    {
        float s = 0.f, sq = 0.f;
#pragma unroll
        for (int c = 0; c < 4; c++) {
            float v = buf[wp][lane + c * 32];
            s += v; sq = fmaf(v, v, sq);
        }
#pragma unroll
        for (int o = 16; o > 0; o >>= 1) {
            s += __shfl_xor_sync(0xffffffff, s, o);
            sq += __shfl_xor_sync(0xffffffff, sq, o);
        }
        if (lane == 0) {
            float mean = s * (1.f / GH);
            float var = sq * (1.f / GH) - mean * mean;
            stat[wp][0] = mean;
            stat[wp][1] = rsqrtf(var + EPS);
        }
    }
    __syncthreads();

    {
        float g = norm_g[col], bb = norm_b[col];
#pragma unroll
        for (int q = 0; q < 4; q++) {
            int r = rg * 4 + q;
            float v = (buf[r][col] - stat[r][0]) * stat[r][1] * g + bb;
            bufT[col * 12 + r] = fmaxf(v, 0.f);
        }
    }
    __syncthreads();

    float a0, a1, a2, a3;
    a0 = a1 = a2 = a3 = lab[col];
#pragma unroll 4
    for (int k = 0; k < GH; k++) {
        float w = law[k * GH + col];
        float4 x = *(const float4*)&bufT[k * 12 + rg * 4];
        a0 = fmaf(x.x, w, a0); a1 = fmaf(x.y, w, a1);
        a2 = fmaf(x.z, w, a2); a3 = fmaf(x.w, w, a3);
    }
    __syncthreads();
#pragma unroll
    for (int q = 0; q < 4; q++) {
        float v = (q == 0) ? a0 : (q == 1) ? a1 : (q == 2) ? a2 : a3;
        bufT[col * 12 + rg * 4 + q] = fmaxf(v, 0.f);
    }
    __syncthreads();

    a0 = a1 = a2 = a3 = lbb[col];
#pragma unroll 4
    for (int k = 0; k < GH; k++) {
        float w = lbw[k * GH + col];
        float4 x = *(const float4*)&bufT[k * 12 + rg * 4];
        a0 = fmaf(x.x, w, a0); a1 = fmaf(x.y, w, a1);
        a2 = fmaf(x.z, w, a2); a3 = fmaf(x.w, w, a3);
    }
    int base = (r0 + rg * 4) * GH + col;
    g_H[base] += a0; g_H[base + GH] += a1; g_H[base + 2 * GH] += a2; g_H[base + 3 * GH] += a3;
}

// ---------------- K6: phi MLP ----------------
__global__ void k_phi(const float* __restrict__ w1, const float* __restrict__ b1,
                      const float* __restrict__ w2, const float* __restrict__ b2) {
    int r0 = blockIdx.x * RT;
    int t = threadIdx.x;              // 256, col = t
    __shared__ __align__(16) float hT[GH * 12];
    __shared__ __align__(16) float h1T[PHI * 12];

    for (int idx = t; idx < RT * GH; idx += 256) {
        int rr = idx >> 7, kk = idx & 127;
        hT[kk * 12 + rr] = g_H[(r0 + rr) * GH + kk];
    }
    __syncthreads();

    float acc[8];
    float bb = b1[t];
#pragma unroll
    for (int q = 0; q < 8; q++) acc[q] = bb;
#pragma unroll 4
    for (int k = 0; k < GH; k++) {
        float w = w1[k * PHI + t];
        float4 xa = *(const float4*)&hT[k * 12];
        float4 xb = *(const float4*)&hT[k * 12 + 4];
        acc[0] = fmaf(xa.x, w, acc[0]); acc[1] = fmaf(xa.y, w, acc[1]);
        acc[2] = fmaf(xa.z, w, acc[2]); acc[3] = fmaf(xa.w, w, acc[3]);
        acc[4] = fmaf(xb.x, w, acc[4]); acc[5] = fmaf(xb.y, w, acc[5]);
        acc[6] = fmaf(xb.z, w, acc[6]); acc[7] = fmaf(xb.w, w, acc[7]);
    }
    *(float4*)&h1T[t * 12] = make_float4(fmaxf(acc[0], 0.f), fmaxf(acc[1], 0.f), fmaxf(acc[2], 0.f), fmaxf(acc[3], 0.f));
    *(float4*)&h1T[t * 12 + 4] = make_float4(fmaxf(acc[4], 0.f), fmaxf(acc[5], 0.f), fmaxf(acc[6], 0.f), fmaxf(acc[7], 0.f));
    __syncthreads();

    bb = b2[t];
#pragma unroll
    for (int q = 0; q < 8; q++) acc[q] = bb;
#pragma unroll 4
    for (int k = 0; k < PHI; k++) {
        float w = w2[k * PHI + t];
        float4 xa = *(const float4*)&h1T[k * 12];
        float4 xb = *(const float4*)&h1T[k * 12 + 4];
        acc[0] = fmaf(xa.x, w, acc[0]); acc[1] = fmaf(xa.y, w, acc[1]);
        acc[2] = fmaf(xa.z, w, acc[2]); acc[3] = fmaf(xa.w, w, acc[3]);
        acc[4] = fmaf(xb.x, w, acc[4]); acc[5] = fmaf(xb.y, w, acc[5]);
        acc[6] = fmaf(xb.z, w, acc[6]); acc[7] = fmaf(xb.w, w, acc[7]);
    }
#pragma unroll
    for (int q = 0; q < 8; q++)
        g_phi[(r0 + q) * PHI + t] = fmaxf(acc[q], 0.f);
}

// ---------------- K7: masked pooling (8 segments of 32 nodes) ----------------
__global__ void k_pool(const float* __restrict__ home_mask) {
    int b = blockIdx.x;
    int seg = blockIdx.y;
    int p = threadIdx.x;          // 256
    const float* pb = g_phi + b * N * PHI;
    const float* hm = home_mask + b * N;
    float hs = 0.f, as = 0.f;
    int n0 = seg * 32;
#pragma unroll 4
    for (int n = n0; n < n0 + 32; n++) {
        float v = pb[n * PHI + p];
        float m = hm[n];
        hs = fmaf(v, m, hs);
        as = fmaf(v, 1.f - m, as);
    }
    g_sums[((seg * 2 + 0) * B + b) * PHI + p] = hs;
    g_sums[((seg * 2 + 1) * B + b) * PHI + p] = as;
}

// ---------------- K8: rho head ----------------
__global__ void k_rho(const float* __restrict__ w1, const float* __restrict__ b1,
                      const float* __restrict__ w2, float* __restrict__ out) {
    int b = blockIdx.x;           // 8
    int t = threadIdx.x;          // 128
    __shared__ float hs[PHI];
    __shared__ float as[PHI];
    __shared__ float red[RHO];
    for (int c = t; c < PHI; c += 128) {
        float h = 0.f, a = 0.f;
#pragma unroll
        for (int seg = 0; seg < 8; seg++) {
            h += g_sums[((seg * 2 + 0) * B + b) * PHI + c];
            a += g_sums[((seg * 2 + 1) * B + b) * PHI + c];
        }
        hs[c] = h; as[c] = a;
    }
    __syncthreads();
    float rh = b1[t], ra = b1[t];
#pragma unroll 4
    for (int k = 0; k < PHI; k++) {
        float w = w1[k * RHO + t];
        rh = fmaf(hs[k], w, rh);
        ra = fmaf(as[k], w, ra);
    }
    rh = fmaxf(rh, 0.f);
    ra = fmaxf(ra, 0.f);
    red[t] = (rh - ra) * w2[t];
    __syncthreads();
    for (int s = RHO / 2; s > 0; s >>= 1) {
        if (t < s) red[t] += red[t + s];
        __syncthreads();
    }
    if (t == 0) out[b] = 0.5f + 0.5f * tanhf(red[0]);
}

// ---------------- launch ----------------
extern "C" void kernel_launch(void* const* d_in, const int* in_sizes, int n_in,
                              void* d_out, int out_size) {
    const float* A        = (const float*)d_in[0];
    const float* X        = (const float*)d_in[1];
    const float* home     = (const float*)d_in[2];
    const float* emb1_w   = (const float*)d_in[3];
    const float* emb1_b   = (const float*)d_in[4];
    const float* emb2_w   = (const float*)d_in[5];
    const float* emb2_b   = (const float*)d_in[6];
    const float* rgcn_w0  = (const float*)d_in[7];
    const float* root0    = (const float*)d_in[8];
    const float* bias0    = (const float*)d_in[9];
    const float* law0     = (const float*)d_in[10];
    const float* lab0     = (const float*)d_in[11];
    const float* lbw0     = (const float*)d_in[12];
    const float* lbb0     = (const float*)d_in[13];
    const float* rgcn_w1  = (const float*)d_in[14];
    const float* root1    = (const float*)d_in[15];
    const float* bias1    = (const float*)d_in[16];
    const float* law1     = (const float*)d_in[17];
    const float* lab1     = (const float*)d_in[18];
    const float* lbw1     = (const float*)d_in[19];
    const float* lbb1     = (const float*)d_in[20];
    const float* norm_g   = (const float*)d_in[21];
    const float* norm_b   = (const float*)d_in[22];
    const float* phi_w1   = (const float*)d_in[23];
    const float* phi_b1   = (const float*)d_in[24];
    const float* phi_w2   = (const float*)d_in[25];
    const float* phi_b2   = (const float*)d_in[26];
    const float* rho_w1   = (const float*)d_in[27];
    const float* rho_b1   = (const float*)d_in[28];
    const float* rho_w2   = (const float*)d_in[29];
    float* out = (float*)d_out;

    k_emb<<<NBLK, 256>>>(X, emb1_w, emb1_b, emb2_w, emb2_b);

    // block 0
    k_reduce<<<256, 256>>>(A);
    k_rgcnmm<<<NBLK, 256>>>(rgcn_w0, root0, bias0);
    k_scatter<<<256, 256>>>(A);
    k_normmlp<<<NBLK, 256>>>(norm_g, norm_b, law0, lab0, lbw0, lbb0);

    // block 1
    k_reduce<<<256, 256>>>(A);
    k_rgcnmm<<<NBLK, 256>>>(rgcn_w1, root1, bias1);
    k_scatter<<<256, 256>>>(A);
    k_normmlp<<<NBLK, 256>>>(norm_g, norm_b, law1, lab1, lbw1, lbb1);

    k_phi<<<NBLK, 256>>>(phi_w1, phi_b1, phi_w2, phi_b2);
    dim3 pg(B, 8);
    k_pool<<<pg, 256>>>(home);
    k_rho<<<B, 128>>>(rho_w1, rho_b1, rho_w2, out);
}

// round 5
// speedup vs baseline: 2.0554x; 1.4519x over previous
#include <cuda_runtime.h>
#include <math.h>

#define B 8
#define N 256
#define BN 2048
#define NID 64
#define V 128
#define GH 128
#define PHI 256
#define RHO 128
#define EPS 1e-5f

// ---------------- scratch ----------------
__device__ float g_H[BN * GH];
__device__ float g_H2[BN * GH];
__device__ float g_phi[BN * PHI];
__device__ float g_sums[8 * 2 * B * PHI];
__device__ float g_msk[BN * N];      // sign(A) in {-1,0,1}, layout [b][i][j]
__device__ float2 g_rcp[BN];         // (1/max(cntPos,1), 1/max(cntNeg,1)) per target j

// ---------------- K0: prep  masks + counts ----------------
__global__ void k_prep(const float* __restrict__ A) {
    int b = blockIdx.x, jc = blockIdx.y * 32;
    int t = threadIdx.x;              // 256
    int j = jc + (t & 31), iseg = t >> 5;   // 8 segs of 32 i
    const float* Ab = A + b * N * N;
    float cp = 0.f, cn = 0.f;
#pragma unroll 4
    for (int ii = 0; ii < 32; ii++) {
        int i = iseg * 32 + ii;
        float a = Ab[i * N + j];
        float p = (a > 0.f) ? 1.f : 0.f;
        float n = (a < 0.f) ? 1.f : 0.f;
        cp += p; cn += n;
        g_msk[((b << 8) + i) * N + j] = p - n;
    }
    __shared__ float sp[8][32], sn[8][32];
    sp[iseg][t & 31] = cp; sn[iseg][t & 31] = cn;
    __syncthreads();
    if (t < 32) {
        float tp = 0.f, tn = 0.f;
#pragma unroll
        for (int s = 0; s < 8; s++) { tp += sp[s][t]; tn += sn[s][t]; }
        g_rcp[(b << 8) + jc + t] = make_float2(1.f / fmaxf(tp, 1.f), 1.f / fmaxf(tn, 1.f));
    }
}

// ---------------- K1: embedding ----------------
__global__ void k_emb(const float* __restrict__ X,
                      const float* __restrict__ W1, const float* __restrict__ b1,
                      const float* __restrict__ W2, const float* __restrict__ b2) {
    int r0 = blockIdx.x * 8;
    int t = threadIdx.x;              // 256
    int col = t & 127, rg = t >> 7;
    __shared__ __align__(16) float xsT[NID * 12];
    __shared__ __align__(16) float h1T[V * 12];

    for (int idx = t; idx < 8 * NID; idx += 256) {
        int rr = idx >> 6, kk = idx & 63;
        xsT[kk * 12 + rr] = X[(r0 + rr) * NID + kk];
    }
    __syncthreads();
    float a0, a1, a2, a3;
    a0 = a1 = a2 = a3 = b1[col];
#pragma unroll 8
    for (int k = 0; k < NID; k++) {
        float w = W1[k * V + col];
        float4 x = *(const float4*)&xsT[k * 12 + rg * 4];
        a0 = fmaf(x.x, w, a0); a1 = fmaf(x.y, w, a1);
        a2 = fmaf(x.z, w, a2); a3 = fmaf(x.w, w, a3);
    }
    *(float4*)&h1T[col * 12 + rg * 4] =
        make_float4(fmaxf(a0, 0.f), fmaxf(a1, 0.f), fmaxf(a2, 0.f), fmaxf(a3, 0.f));
    __syncthreads();
    a0 = a1 = a2 = a3 = b2[col];
#pragma unroll 8
    for (int k = 0; k < V; k++) {
        float w = W2[k * V + col];
        float4 x = *(const float4*)&h1T[k * 12 + rg * 4];
        a0 = fmaf(x.x, w, a0); a1 = fmaf(x.y, w, a1);
        a2 = fmaf(x.z, w, a2); a3 = fmaf(x.w, w, a3);
    }
    int base = (r0 + rg * 4) * V + col;
    g_H[base] = a0; g_H[base + V] = a1; g_H[base + 2 * V] = a2; g_H[base + 3 * V] = a3;
}

// ---------------- K2: fused RGCN (masked-mean reduce + 3-way matmul) ----------------
// block = (b, j-tile of 8); 512 threads = 4 i-segments x 128 cols
__global__ void __launch_bounds__(512) k_rgcn(const float* __restrict__ Wrel,
                                              const float* __restrict__ Wroot,
                                              const float* __restrict__ bias) {
    int b = blockIdx.x >> 5;
    int j0 = (blockIdx.x & 31) * 8;
    int t = threadIdx.x;
    int col = t & 127, iseg = t >> 7;     // 0..3
    __shared__ __align__(16) float msk_s[N][8];     // 8KB
    __shared__ float sAccS[8][128], sAccA[8][128];  // 8KB
    __shared__ __align__(16) float hrT[GH * 12];    // 6KB
    __shared__ __align__(16) float snT[GH * 12];
    __shared__ __align__(16) float spT[GH * 12];
    __shared__ float2 rcp_s[8];

    // stage signed masks for all 256 sources x 8 targets
    for (int idx = t; idx < N * 8; idx += 512) {
        int i = idx >> 3, jj = idx & 7;
        msk_s[i][jj] = g_msk[((b << 8) + i) * N + j0 + jj];
    }
    if (t < 8) rcp_s[t] = g_rcp[(b << 8) + j0 + t];
    __syncthreads();

    float accS[8], accA[8];
#pragma unroll
    for (int jj = 0; jj < 8; jj++) { accS[jj] = 0.f; accA[jj] = 0.f; }
    const float* Hb = g_H + ((b << 8) + (iseg << 6)) * V + col;
#pragma unroll 4
    for (int ii = 0; ii < 64; ii++) {
        float h = Hb[ii * V];
        int i = (iseg << 6) + ii;
        float4 m1 = *(const float4*)&msk_s[i][0];
        float4 m2 = *(const float4*)&msk_s[i][4];
        accS[0] = fmaf(m1.x, h, accS[0]); accA[0] = fmaf(fabsf(m1.x), h, accA[0]);
        accS[1] = fmaf(m1.y, h, accS[1]); accA[1] = fmaf(fabsf(m1.y), h, accA[1]);
        accS[2] = fmaf(m1.z, h, accS[2]); accA[2] = fmaf(fabsf(m1.z), h, accA[2]);
        accS[3] = fmaf(m1.w, h, accS[3]); accA[3] = fmaf(fabsf(m1.w), h, accA[3]);
        accS[4] = fmaf(m2.x, h, accS[4]); accA[4] = fmaf(fabsf(m2.x), h, accA[4]);
        accS[5] = fmaf(m2.y, h, accS[5]); accA[5] = fmaf(fabsf(m2.y), h, accA[5]);
        accS[6] = fmaf(m2.z, h, accS[6]); accA[6] = fmaf(fabsf(m2.z), h, accA[6]);
        accS[7] = fmaf(m2.w, h, accS[7]); accA[7] = fmaf(fabsf(m2.w), h, accA[7]);
    }
    // 4-pass combine into sAcc
#pragma unroll
    for (int s = 0; s < 4; s++) {
        if (iseg == s) {
            if (s == 0) {
#pragma unroll
                for (int jj = 0; jj < 8; jj++) { sAccS[jj][col] = accS[jj]; sAccA[jj][col] = accA[jj]; }
            } else {
#pragma unroll
                for (int jj = 0; jj < 8; jj++) { sAccS[jj][col] += accS[jj]; sAccA[jj][col] += accA[jj]; }
            }
        }
        __syncthreads();
    }
    // normalize + transpose (iseg 0), stage H rows (all threads)
    if (iseg == 0) {
#pragma unroll
        for (int jj = 0; jj < 8; jj++) {
            float sa = sAccA[jj][col], ss = sAccS[jj][col];
            spT[col * 12 + jj] = (sa + ss) * 0.5f * rcp_s[jj].x;
            snT[col * 12 + jj] = (sa - ss) * 0.5f * rcp_s[jj].y;
        }
    }
    for (int idx = t; idx < 8 * GH; idx += 512) {
        int rr = idx >> 7, kk = idx & 127;
        hrT[kk * 12 + rr] = g_H[((b << 8) + j0 + rr) * GH + kk];
    }
    __syncthreads();

    // matmul: rg = iseg handles rows rg*2, rg*2+1
    const float* W0 = Wrel;
    const float* W1 = Wrel + V * GH;
    float a0, a1;
    a0 = a1 = bias[col];
#pragma unroll 4
    for (int k = 0; k < GH; k++) {
        float wr = Wroot[k * GH + col];
        float w0 = W0[k * GH + col];
        float w1 = W1[k * GH + col];
        float2 h = *(const float2*)&hrT[k * 12 + iseg * 2];
        float2 sn = *(const float2*)&snT[k * 12 + iseg * 2];
        float2 sp = *(const float2*)&spT[k * 12 + iseg * 2];
        a0 = fmaf(h.x, wr, a0);  a1 = fmaf(h.y, wr, a1);
        a0 = fmaf(sn.x, w0, a0); a1 = fmaf(sn.y, w0, a1);
        a0 = fmaf(sp.x, w1, a0); a1 = fmaf(sp.y, w1, a1);
    }
    int base = ((b << 8) + j0 + iseg * 2) * GH + col;
    g_H2[base] = a0; g_H2[base + GH] = a1;
}

// ---------------- K3: fused scatter + layernorm + MLP + H+= ----------------
// block = (b, i-tile of 8); 512 threads = 4 j-segments x 128 cols
__global__ void __launch_bounds__(512) k_scat(const float* __restrict__ A,
                                              const float* __restrict__ norm_g, const float* __restrict__ norm_b,
                                              const float* __restrict__ law, const float* __restrict__ lab,
                                              const float* __restrict__ lbw, const float* __restrict__ lbb) {
    int b = blockIdx.x >> 5;
    int i0 = (blockIdx.x & 31) * 8;
    int t = threadIdx.x;
    int col = t & 127, jseg = t >> 7;     // 0..3
    int wp = t >> 5, lane = t & 31;
    __shared__ __align__(16) float aabT[N * 8];     // [j][i-in-tile] 8KB
    __shared__ float buf[8][128];                   // 4KB (acc + post-norm staging)
    __shared__ __align__(16) float bufT[GH * 12];   // 6KB
    __shared__ float stat[8][2];

    // stage |A| transposed: aabT[j][q] = |A[b][i0+q][j]|
    {
        int jj = t & 255, half = t >> 8;   // half: rows 0-3 / 4-7
        const float* Ar = A + (b * N + i0 + half * 4) * N + jj;
        float a_[4];
#pragma unroll
        for (int q = 0; q < 4; q++) a_[q] = fabsf(Ar[q * N]);
        *(float4*)&aabT[jj * 8 + half * 4] = make_float4(a_[0], a_[1], a_[2], a_[3]);
    }
    __syncthreads();

    float acc[8];
#pragma unroll
    for (int q = 0; q < 8; q++) acc[q] = 0.f;
    const float* H2b = g_H2 + ((b << 8) + (jseg << 6)) * GH + col;
#pragma unroll 4
    for (int jj = 0; jj < 64; jj++) {
        float h2 = H2b[jj * GH];
        int j = (jseg << 6) + jj;
        float4 m1 = *(const float4*)&aabT[j * 8];
        float4 m2 = *(const float4*)&aabT[j * 8 + 4];
        acc[0] = fmaf(m1.x, h2, acc[0]); acc[1] = fmaf(m1.y, h2, acc[1]);
        acc[2] = fmaf(m1.z, h2, acc[2]); acc[3] = fmaf(m1.w, h2, acc[3]);
        acc[4] = fmaf(m2.x, h2, acc[4]); acc[5] = fmaf(m2.y, h2, acc[5]);
        acc[6] = fmaf(m2.z, h2, acc[6]); acc[7] = fmaf(m2.w, h2, acc[7]);
    }
#pragma unroll
    for (int s = 0; s < 4; s++) {
        if (jseg == s) {
            if (s == 0) {
#pragma unroll
                for (int q = 0; q < 8; q++) buf[q][col] = acc[q];
            } else {
#pragma unroll
                for (int q = 0; q < 8; q++) buf[q][col] += acc[q];
            }
        }
        __syncthreads();
    }

    // layernorm stats: warps 0..7 -> row wp
    if (wp < 8) {
        float s = 0.f, sq = 0.f;
#pragma unroll
        for (int c = 0; c < 4; c++) {
            float v = buf[wp][lane + c * 32];
            s += v; sq = fmaf(v, v, sq);
        }
#pragma unroll
        for (int o = 16; o > 0; o >>= 1) {
            s += __shfl_xor_sync(0xffffffff, s, o);
            sq += __shfl_xor_sync(0xffffffff, sq, o);
        }
        if (lane == 0) {
            float mean = s * (1.f / GH);
            float var = sq * (1.f / GH) - mean * mean;
            stat[wp][0] = mean;
            stat[wp][1] = rsqrtf(var + EPS);
        }
    }
    __syncthreads();
    // normalize + relu + transpose into bufT
    for (int idx = t; idx < 8 * GH; idx += 512) {
        int r = idx & 7, cc = idx >> 3;
        float v = (buf[r][cc] - stat[r][0]) * stat[r][1] * norm_g[cc] + norm_b[cc];
        bufT[cc * 12 + r] = fmaxf(v, 0.f);
    }
    __syncthreads();

    // MLP layer 1 (rg = jseg, 2 rows each)
    float a0, a1;
    a0 = a1 = lab[col];
#pragma unroll 8
    for (int k = 0; k < GH; k++) {
        float w = law[k * GH + col];
        float2 x = *(const float2*)&bufT[k * 12 + jseg * 2];
        a0 = fmaf(x.x, w, a0); a1 = fmaf(x.y, w, a1);
    }
    __syncthreads();
    *(float2*)&bufT[col * 12 + jseg * 2] = make_float2(fmaxf(a0, 0.f), fmaxf(a1, 0.f));
    __syncthreads();

    // MLP layer 2 + H +=
    a0 = a1 = lbb[col];
#pragma unroll 8
    for (int k = 0; k < GH; k++) {
        float w = lbw[k * GH + col];
        float2 x = *(const float2*)&bufT[k * 12 + jseg * 2];
        a0 = fmaf(x.x, w, a0); a1 = fmaf(x.y, w, a1);
    }
    int base = ((b << 8) + i0 + jseg * 2) * GH + col;
    g_H[base] += a0; g_H[base + GH] += a1;
}

// ---------------- K4: phi MLP (512 threads, 8 rows) ----------------
__global__ void __launch_bounds__(512) k_phi(const float* __restrict__ w1, const float* __restrict__ b1,
                                             const float* __restrict__ w2, const float* __restrict__ b2) {
    int r0 = blockIdx.x * 8;
    int t = threadIdx.x;
    int col = t & 255, rg = t >> 8;   // rg 0/1, 4 rows each
    __shared__ __align__(16) float hT[GH * 12];
    __shared__ __align__(16) float h1T[PHI * 12];

    for (int idx = t; idx < 8 * GH; idx += 512) {
        int rr = idx >> 7, kk = idx & 127;
        hT[kk * 12 + rr] = g_H[(r0 + rr) * GH + kk];
    }
    __syncthreads();
    float a0, a1, a2, a3;
    a0 = a1 = a2 = a3 = b1[col];
#pragma unroll 8
    for (int k = 0; k < GH; k++) {
        float w = w1[k * PHI + col];
        float4 x = *(const float4*)&hT[k * 12 + rg * 4];
        a0 = fmaf(x.x, w, a0); a1 = fmaf(x.y, w, a1);
        a2 = fmaf(x.z, w, a2); a3 = fmaf(x.w, w, a3);
    }
    *(float4*)&h1T[col * 12 + rg * 4] =
        make_float4(fmaxf(a0, 0.f), fmaxf(a1, 0.f), fmaxf(a2, 0.f), fmaxf(a3, 0.f));
    __syncthreads();
    a0 = a1 = a2 = a3 = b2[col];
#pragma unroll 8
    for (int k = 0; k < PHI; k++) {
        float w = w2[k * PHI + col];
        float4 x = *(const float4*)&h1T[k * 12 + rg * 4];
        a0 = fmaf(x.x, w, a0); a1 = fmaf(x.y, w, a1);
        a2 = fmaf(x.z, w, a2); a3 = fmaf(x.w, w, a3);
    }
    int base = (r0 + rg * 4) * PHI + col;
    g_phi[base] = fmaxf(a0, 0.f);
    g_phi[base + PHI] = fmaxf(a1, 0.f);
    g_phi[base + 2 * PHI] = fmaxf(a2, 0.f);
    g_phi[base + 3 * PHI] = fmaxf(a3, 0.f);
}

// ---------------- K5: masked pooling (8 segments of 32 nodes) ----------------
__global__ void k_pool(const float* __restrict__ home_mask) {
    int b = blockIdx.x;
    int seg = blockIdx.y;
    int p = threadIdx.x;          // 256
    const float* pb = g_phi + b * N * PHI;
    const float* hm = home_mask + b * N;
    float hs = 0.f, as = 0.f;
    int n0 = seg * 32;
#pragma unroll 8
    for (int n = n0; n < n0 + 32; n++) {
        float v = pb[n * PHI + p];
        float m = hm[n];
        hs = fmaf(v, m, hs);
        as = fmaf(v, 1.f - m, as);
    }
    g_sums[((seg * 2 + 0) * B + b) * PHI + p] = hs;
    g_sums[((seg * 2 + 1) * B + b) * PHI + p] = as;
}

// ---------------- K6: rho head ----------------
__global__ void k_rho(const float* __restrict__ w1, const float* __restrict__ b1,
                      const float* __restrict__ w2, float* __restrict__ out) {
    int b = blockIdx.x;           // 8
    int t = threadIdx.x;          // 128
    __shared__ float hs[PHI];
    __shared__ float as[PHI];
    __shared__ float red[RHO];
    for (int c = t; c < PHI; c += 128) {
        float h = 0.f, a = 0.f;
#pragma unroll
        for (int seg = 0; seg < 8; seg++) {
            h += g_sums[((seg * 2 + 0) * B + b) * PHI + c];
            a += g_sums[((seg * 2 + 1) * B + b) * PHI + c];
        }
        hs[c] = h; as[c] = a;
    }
    __syncthreads();
    float rh = b1[t], ra = b1[t];
#pragma unroll 8
    for (int k = 0; k < PHI; k++) {
        float w = w1[k * RHO + t];
        rh = fmaf(hs[k], w, rh);
        ra = fmaf(as[k], w, ra);
    }
    rh = fmaxf(rh, 0.f);
    ra = fmaxf(ra, 0.f);
    red[t] = (rh - ra) * w2[t];
    __syncthreads();
    for (int s = RHO / 2; s > 0; s >>= 1) {
        if (t < s) red[t] += red[t + s];
        __syncthreads();
    }
    if (t == 0) out[b] = 0.5f + 0.5f * tanhf(red[0]);
}

// ---------------- launch ----------------
extern "C" void kernel_launch(void* const* d_in, const int* in_sizes, int n_in,
                              void* d_out, int out_size) {
    const float* A        = (const float*)d_in[0];
    const float* X        = (const float*)d_in[1];
    const float* home     = (const float*)d_in[2];
    const float* emb1_w   = (const float*)d_in[3];
    const float* emb1_b   = (const float*)d_in[4];
    const float* emb2_w   = (const float*)d_in[5];
    const float* emb2_b   = (const float*)d_in[6];
    const float* rgcn_w0  = (const float*)d_in[7];
    const float* root0    = (const float*)d_in[8];
    const float* bias0    = (const float*)d_in[9];
    const float* law0     = (const float*)d_in[10];
    const float* lab0     = (const float*)d_in[11];
    const float* lbw0     = (const float*)d_in[12];
    const float* lbb0     = (const float*)d_in[13];
    const float* rgcn_w1  = (const float*)d_in[14];
    const float* root1    = (const float*)d_in[15];
    const float* bias1    = (const float*)d_in[16];
    const float* law1     = (const float*)d_in[17];
    const float* lab1     = (const float*)d_in[18];
    const float* lbw1     = (const float*)d_in[19];
    const float* lbb1     = (const float*)d_in[20];
    const float* norm_g   = (const float*)d_in[21];
    const float* norm_b   = (const float*)d_in[22];
    const float* phi_w1   = (const float*)d_in[23];
    const float* phi_b1   = (const float*)d_in[24];
    const float* phi_w2   = (const float*)d_in[25];
    const float* phi_b2   = (const float*)d_in[26];
    const float* rho_w1   = (const float*)d_in[27];
    const float* rho_b1   = (const float*)d_in[28];
    const float* rho_w2   = (const float*)d_in[29];
    float* out = (float*)d_out;

    dim3 pgrid(8, 8);
    k_prep<<<pgrid, 256>>>(A);
    k_emb<<<256, 256>>>(X, emb1_w, emb1_b, emb2_w, emb2_b);

    k_rgcn<<<256, 512>>>(rgcn_w0, root0, bias0);
    k_scat<<<256, 512>>>(A, norm_g, norm_b, law0, lab0, lbw0, lbb0);

    k_rgcn<<<256, 512>>>(rgcn_w1, root1, bias1);
    k_scat<<<256, 512>>>(A, norm_g, norm_b, law1, lab1, lbw1, lbb1);

    k_phi<<<256, 512>>>(phi_w1, phi_b1, phi_w2, phi_b2);
    dim3 pg(B, 8);
    k_pool<<<pg, 256>>>(home);
    k_rho<<<B, 128>>>(rho_w1, rho_b1, rho_w2, out);
}